// round 9
// baseline (speedup 1.0000x reference)
#include <cuda_runtime.h>

#define BB 256
#define HH 224
#define WW 224
#define HW (HH*WW)          // 50176
#define W4 (WW/4)           // 56
#define PARTS 4
#define ROWS_PER_PART (HH/PARTS)   // 56
#define TILE_ROWS 8
#define SRC_ROWS 9
#define NTILES (HH/TILE_ROWS)      // 28

__device__ float g_partial[BB*PARTS];

// ---------------- Kernel 1: per-image mean of grayscale(clip(bf*img)) ----------------
__global__ void __launch_bounds__(256) mean_kernel(const float* __restrict__ img,
                                                   const float* __restrict__ u_jitter,
                                                   const float* __restrict__ u_bright)
{
    int b = blockIdx.y;
    int part = blockIdx.x;
    __shared__ float red[8];
    if (u_jitter[b] >= 0.8f) {           // mean unused for jitter-off images
        if (threadIdx.x == 0) g_partial[b*PARTS+part] = 0.0f;
        return;
    }
    float bf = 1.0f + (2.0f*u_bright[b] - 1.0f)*0.2f;
    const float4* base = (const float4*)(img + (size_t)b*3*HW);
    int p0 = (part*ROWS_PER_PART*WW) >> 2;
    const int N4 = (ROWS_PER_PART*WW) >> 2;   // 3136
    float sum = 0.0f;
    for (int i = threadIdx.x; i < N4; i += blockDim.x) {
        int p = p0 + i;
        float4 r4 = base[p];
        float4 g4 = base[(HW>>2)+p];
        float4 b4 = base[(2*(HW>>2))+p];
        #pragma unroll
        for (int j = 0; j < 4; j++) {
            float r  = __saturatef(bf*((const float*)&r4)[j]);
            float g  = __saturatef(bf*((const float*)&g4)[j]);
            float bl = __saturatef(bf*((const float*)&b4)[j]);
            sum += 0.299f*r + 0.587f*g + 0.114f*bl;
        }
    }
    // warp + smem reduce
    #pragma unroll
    for (int s = 16; s > 0; s >>= 1) sum += __shfl_xor_sync(0xffffffffu, sum, s);
    if ((threadIdx.x & 31) == 0) red[threadIdx.x >> 5] = sum;
    __syncthreads();
    if (threadIdx.x < 8) {
        float v = red[threadIdx.x];
        #pragma unroll
        for (int s = 4; s > 0; s >>= 1) v += __shfl_xor_sync(0xffu, v, s);
        if (threadIdx.x == 0) g_partial[b*PARTS+part] = v;
    }
}

// ---------------- color jitter for one pixel (streamlined) ----------------
// cm = (1-cf)*mg, omsf = 1-sf, hb = 1 + hue   (hoisted per image)
__device__ __forceinline__ void jitter_px(float& r, float& g, float& bl,
                                          float bf, float cf, float cm,
                                          float sf, float omsf, float hb)
{
    // brightness blend with zeros (saturate folds into the MUL)
    r = __saturatef(bf*r); g = __saturatef(bf*g); bl = __saturatef(bf*bl);
    // contrast blend with mean gray
    r  = __saturatef(fmaf(cf, r,  cm));
    g  = __saturatef(fmaf(cf, g,  cm));
    bl = __saturatef(fmaf(cf, bl, cm));
    // saturation blend with per-pixel gray
    float gray = fmaf(0.299f, r, fmaf(0.587f, g, 0.114f*bl));
    float sg = omsf*gray;
    r  = __saturatef(fmaf(sf, r,  sg));
    g  = __saturatef(fmaf(sf, g,  sg));
    bl = __saturatef(fmaf(sf, bl, sg));
    // hue rotate: RGB -> (h, v, chroma) -> shift -> RGB (branch-free, v*s == chroma)
    float maxc = fmaxf(fmaxf(r,g),bl);
    float minc = fminf(fminf(r,g),bl);
    float v  = maxc;
    float cr = maxc - minc;
    float inv = __fdividef(1.0f, (cr == 0.0f) ? 1.0f : cr);
    // delta-form sector offset: (bc-gc)=(g-b)*inv, (2+rc-bc)=2+(b-r)*inv, (4+gc-rc)=4+(r-g)*inv
    float d    = (maxc == r) ? (g - bl) : (maxc == g) ? (bl - r) : (r - g);
    float base = (maxc == r) ? 0.0f     : (maxc == g) ? 2.0f     : 4.0f;
    float h = fmaf(fmaf(d, inv, base), 1.0f/6.0f, hb);   // h0/6 + 1 + hue
    h -= floorf(h);
    float h6 = h*6.0f;                      // in [0, 6)
    // out_n = v - chroma * clamp01(min(k, 4-k)),  k = (n + h6) mod 6
    float kr = 5.0f + h6; kr = (kr >= 6.0f) ? (kr - 6.0f) : kr;
    float kg = 3.0f + h6; kg = (kg >= 6.0f) ? (kg - 6.0f) : kg;
    float kb = 1.0f + h6; kb = (kb >= 6.0f) ? (kb - 6.0f) : kb;
    r  = __saturatef(fmaf(-cr, __saturatef(fminf(kr, 4.0f - kr)), v));
    g  = __saturatef(fmaf(-cr, __saturatef(fminf(kg, 4.0f - kg)), v));
    bl = __saturatef(fmaf(-cr, __saturatef(fminf(kb, 4.0f - kb)), v));
}

// ---------------- Kernel 2: fused jitter + crop-resize ----------------
__global__ void __launch_bounds__(256, 6) aug_kernel(const float* __restrict__ img,
                                                  const float* __restrict__ u_jitter,
                                                  const float* __restrict__ u_bright,
                                                  const float* __restrict__ u_contrast,
                                                  const float* __restrict__ u_sat,
                                                  const float* __restrict__ u_hue,
                                                  const float* __restrict__ u_crop,
                                                  const float* __restrict__ u_scale,
                                                  const float* __restrict__ u_top,
                                                  const float* __restrict__ u_left,
                                                  float* __restrict__ out)
{
    __shared__ float  sm[3][SRC_ROWS][WW];   // 24192 B
    __shared__ float4 s_xm[WW];              //  3584 B  {wx, x0, x1}
    __shared__ float4 s_ym[TILE_ROWS];       //   128 B  {wy, y0*WW, y1*WW}

    int b   = blockIdx.y;
    int ty0 = blockIdx.x * TILE_ROWS;

    bool jit = (u_jitter[b] < 0.8f);
    bool crp = (u_crop[b]   < 0.5f);

    float bf = 1.0f + (2.0f*u_bright[b]   - 1.0f)*0.2f;
    float cf = 1.0f + (2.0f*u_contrast[b] - 1.0f)*0.2f;
    float sf = 1.0f + (2.0f*u_sat[b]      - 1.0f)*0.2f;
    float hb = 1.0f + (2.0f*u_hue[b] - 1.0f)*0.05f;     // 1 + hue
    float omsf = 1.0f - sf;
    float cm = 0.0f;
    if (jit) {
        float acc = 0.0f;
        #pragma unroll
        for (int k = 0; k < PARTS; k++) acc += g_partial[b*PARTS+k];
        cm = (1.0f - cf) * (acc * (1.0f/(float)HW));
    }

    const float* src = img + (size_t)b*3*HW;
    float*       dst = out + (size_t)b*3*HW;

    if (!crp) {
        // output = jittered (or raw) input rows, identity geometry
        const float4* s4 = (const float4*)src;
        float4*       d4 = (float4*)dst;
        if (!jit) {
            #pragma unroll
            for (int c = 0; c < 3; c++) {
                int base = (c*HW + ty0*WW) >> 2;
                for (int i = threadIdx.x; i < (TILE_ROWS*WW)>>2; i += blockDim.x)
                    d4[base+i] = s4[base+i];
            }
        } else {
            int base = (ty0*WW) >> 2;
            for (int i = threadIdx.x; i < (TILE_ROWS*WW)>>2; i += blockDim.x) {
                int p = base + i;
                float4 r4 = s4[p];
                float4 g4 = s4[(HW>>2)+p];
                float4 b4 = s4[(2*(HW>>2))+p];
                #pragma unroll
                for (int j = 0; j < 4; j++) {
                    float r  = ((const float*)&r4)[j];
                    float g  = ((const float*)&g4)[j];
                    float bl = ((const float*)&b4)[j];
                    jitter_px(r,g,bl, bf,cf,cm,sf,omsf,hb);
                    ((float*)&r4)[j] = r; ((float*)&g4)[j] = g; ((float*)&b4)[j] = bl;
                }
                d4[p] = r4;
                d4[(HW>>2)+p] = g4;
                d4[(2*(HW>>2))+p] = b4;
            }
        }
        return;
    }

    // ---- crop geometry: must match JAX fp32 op-for-op (floor decisions) ----
    float scale = __fadd_rn(0.85f, __fmul_rn((1.0f - 0.85f), u_scale[b]));
    float chf   = floorf(__fmul_rn(224.0f, scale));
    float cwf   = chf;   // H == W
    float hm    = __fadd_rn(__fsub_rn(224.0f, chf), 1.0f);
    float topf  = fminf(fmaxf(floorf(__fmul_rn(u_top[b],  hm)), 0.0f), 224.0f - chf);
    float leftf = fminf(fmaxf(floorf(__fmul_rn(u_left[b], hm)), 0.0f), 224.0f - cwf);

    const float inv224 = 1.0f/224.0f;

    // source row window for this tile (ys monotone in y; same formula as meta below)
    float ys0 = fminf(fmaxf(topf + ((float)ty0 + 0.5f)*chf*inv224 - 0.5f, 0.0f), 223.0f);
    int ry0 = (int)floorf(ys0);

    // ---- geometry meta tables (computed ONCE per CTA, identical expressions) ----
    for (int ox = threadIdx.x; ox < WW; ox += blockDim.x) {
        float xs = fminf(fmaxf(leftf + ((float)ox + 0.5f)*cwf*inv224 - 0.5f, 0.0f), 223.0f);
        float x0f = floorf(xs);
        int x0 = (int)x0f;
        int x1 = min(x0 + 1, WW-1);
        s_xm[ox] = make_float4(xs - x0f, __int_as_float(x0), __int_as_float(x1), 0.0f);
    }
    if (threadIdx.x < TILE_ROWS) {
        int oy = ty0 + threadIdx.x;
        float ys = fminf(fmaxf(topf + ((float)oy + 0.5f)*chf*inv224 - 0.5f, 0.0f), 223.0f);
        float y0f = floorf(ys);
        int y0 = (int)y0f - ry0;
        int y1 = min((int)y0f + 1, HH-1) - ry0;
        s_ym[threadIdx.x] = make_float4(ys - y0f, __int_as_float(y0*WW), __int_as_float(y1*WW), 0.0f);
    }

    // ---- phase 1: load + jitter SRC_ROWS x 224 slab into smem ----
    for (int idx = threadIdx.x; idx < SRC_ROWS*WW; idx += blockDim.x) {
        int row = idx / WW;
        int col = idx - row*WW;
        int srow = min(ry0 + row, HH-1);
        int p = srow*WW + col;
        float r = src[p], g = src[HW+p], bl = src[2*HW+p];
        if (jit) jitter_px(r,g,bl, bf,cf,cm,sf,omsf,hb);
        sm[0][row][col] = r;
        sm[1][row][col] = g;
        sm[2][row][col] = bl;
    }
    __syncthreads();

    // ---- phase 2: bilinear sample TILE_ROWS x 224 output, 4 px per thread ----
    const float* sp = &sm[0][0][0];
    for (int idx = threadIdx.x; idx < TILE_ROWS*W4; idx += blockDim.x) {
        int ry = idx / W4;
        int c4 = idx - ry*W4;
        float4 ym = s_ym[ry];
        float wy = ym.x;
        int yo0 = __float_as_int(ym.y);
        int yo1 = __float_as_int(ym.z);

        float4 o0, o1, o2;
        #pragma unroll
        for (int j = 0; j < 4; j++) {
            float4 xm = s_xm[c4*4 + j];
            float wx = xm.x;
            int x0 = __float_as_int(xm.y);
            int x1 = __float_as_int(xm.z);
            #pragma unroll
            for (int c = 0; c < 3; c++) {
                const float* p = sp + c*(SRC_ROWS*WW);
                float a  = p[yo0+x0], bq = p[yo0+x1];
                float cq = p[yo1+x0], dq = p[yo1+x1];
                float row0 = fmaf(wx, bq - a,  a);
                float row1 = fmaf(wx, dq - cq, cq);
                float val  = fmaf(wy, row1 - row0, row0);
                if (c == 0) ((float*)&o0)[j] = val;
                else if (c == 1) ((float*)&o1)[j] = val;
                else ((float*)&o2)[j] = val;
            }
        }

        float4* d4 = (float4*)dst;
        int oy = ty0 + ry;
        int po4 = oy*W4 + c4;
        d4[po4]             = o0;
        d4[(HW>>2) + po4]   = o1;
        d4[2*(HW>>2) + po4] = o2;
    }
}

extern "C" void kernel_launch(void* const* d_in, const int* in_sizes, int n_in,
                              void* d_out, int out_size)
{
    const float* img        = (const float*)d_in[0];
    const float* u_jitter   = (const float*)d_in[1];
    const float* u_bright   = (const float*)d_in[2];
    const float* u_contrast = (const float*)d_in[3];
    const float* u_sat      = (const float*)d_in[4];
    const float* u_hue      = (const float*)d_in[5];
    const float* u_crop     = (const float*)d_in[6];
    const float* u_scale    = (const float*)d_in[7];
    const float* u_top      = (const float*)d_in[8];
    const float* u_left     = (const float*)d_in[9];
    float* out = (float*)d_out;

    dim3 g1(PARTS, BB);
    mean_kernel<<<g1, 256>>>(img, u_jitter, u_bright);

    dim3 g2(NTILES, BB);
    aug_kernel<<<g2, 256>>>(img, u_jitter, u_bright, u_contrast, u_sat, u_hue,
                            u_crop, u_scale, u_top, u_left, out);
}

// round 10
// speedup vs baseline: 1.0874x; 1.0874x over previous
#include <cuda_runtime.h>

#define BB 256
#define HH 224
#define WW 224
#define HW (HH*WW)          // 50176
#define W4 (WW/4)           // 56
#define PARTS 4
#define ROWS_PER_PART (HH/PARTS)   // 56
#define TILE_ROWS 8
#define SRC_ROWS 9
#define NTILES (HH/TILE_ROWS)      // 28

__device__ float g_partial[BB*PARTS];

// ---------------- Kernel 1: per-image mean of grayscale(clip(bf*img)) ----------------
__global__ void __launch_bounds__(256) mean_kernel(const float* __restrict__ img,
                                                   const float* __restrict__ u_jitter,
                                                   const float* __restrict__ u_bright)
{
    int b = blockIdx.y;
    int part = blockIdx.x;
    __shared__ float red[8];
    if (u_jitter[b] >= 0.8f) {           // mean unused for jitter-off images
        if (threadIdx.x == 0) g_partial[b*PARTS+part] = 0.0f;
        return;
    }
    float bf = 1.0f + (2.0f*u_bright[b] - 1.0f)*0.2f;
    const float4* base = (const float4*)(img + (size_t)b*3*HW);
    int p0 = (part*ROWS_PER_PART*WW) >> 2;
    const int N4 = (ROWS_PER_PART*WW) >> 2;   // 3136
    float sum = 0.0f;
    for (int i = threadIdx.x; i < N4; i += blockDim.x) {
        int p = p0 + i;
        float4 r4 = base[p];
        float4 g4 = base[(HW>>2)+p];
        float4 b4 = base[(2*(HW>>2))+p];
        #pragma unroll
        for (int j = 0; j < 4; j++) {
            float r  = __saturatef(bf*((const float*)&r4)[j]);
            float g  = __saturatef(bf*((const float*)&g4)[j]);
            float bl = __saturatef(bf*((const float*)&b4)[j]);
            sum += 0.299f*r + 0.587f*g + 0.114f*bl;
        }
    }
    // warp + smem reduce
    #pragma unroll
    for (int s = 16; s > 0; s >>= 1) sum += __shfl_xor_sync(0xffffffffu, sum, s);
    if ((threadIdx.x & 31) == 0) red[threadIdx.x >> 5] = sum;
    __syncthreads();
    if (threadIdx.x < 8) {
        float v = red[threadIdx.x];
        #pragma unroll
        for (int s = 4; s > 0; s >>= 1) v += __shfl_xor_sync(0xffu, v, s);
        if (threadIdx.x == 0) g_partial[b*PARTS+part] = v;
    }
}

// ---------------- color jitter for one pixel (streamlined v2) ----------------
// cm = (1-cf)*mg, omsf = 1-sf, hb = 1 + hue   (hoisted per image)
__device__ __forceinline__ void jitter_px(float& r, float& g, float& bl,
                                          float bf, float cf, float cm,
                                          float sf, float omsf, float hb)
{
    // brightness blend with zeros (saturate folds into the MUL)
    r = __saturatef(bf*r); g = __saturatef(bf*g); bl = __saturatef(bf*bl);
    // contrast blend with mean gray
    r  = __saturatef(fmaf(cf, r,  cm));
    g  = __saturatef(fmaf(cf, g,  cm));
    bl = __saturatef(fmaf(cf, bl, cm));
    // saturation blend with per-pixel gray
    float gray = fmaf(0.299f, r, fmaf(0.587f, g, 0.114f*bl));
    float sg = omsf*gray;
    r  = __saturatef(fmaf(sf, r,  sg));
    g  = __saturatef(fmaf(sf, g,  sg));
    bl = __saturatef(fmaf(sf, bl, sg));
    // hue rotate: RGB -> (h, v, chroma) -> shift -> RGB (branch-free, v*s == chroma)
    float maxc = fmaxf(fmaxf(r,g),bl);
    float minc = fminf(fminf(r,g),bl);
    float v  = maxc;
    float cr = maxc - minc;
    float inv = __fdividef(1.0f, (cr == 0.0f) ? 1.0f : cr);
    // delta-form sector offset: (bc-gc)=(g-b)*inv, (2+rc-bc)=2+(b-r)*inv, (4+gc-rc)=4+(r-g)*inv
    float d    = (maxc == r) ? (g - bl) : (maxc == g) ? (bl - r) : (r - g);
    float base = (maxc == r) ? 0.0f     : (maxc == g) ? 2.0f     : 4.0f;
    float h = fmaf(fmaf(d, inv, base), 1.0f/6.0f, hb);   // h0/6 + 1 + hue
    h -= floorf(h);
    float h6 = h*6.0f;                      // in [0, 6)
    // out_n = v - chroma * clamp01(min(k, 4-k)),  k = (n + h6) mod 6
    float kr = 5.0f + h6; kr = (kr >= 6.0f) ? (kr - 6.0f) : kr;
    float kg = 3.0f + h6; kg = (kg >= 6.0f) ? (kg - 6.0f) : kg;
    float kb = 1.0f + h6; kb = (kb >= 6.0f) ? (kb - 6.0f) : kb;
    r  = __saturatef(fmaf(-cr, __saturatef(fminf(kr, 4.0f - kr)), v));
    g  = __saturatef(fmaf(-cr, __saturatef(fminf(kg, 4.0f - kg)), v));
    bl = __saturatef(fmaf(-cr, __saturatef(fminf(kb, 4.0f - kb)), v));
}

// ---------------- Kernel 2: fused jitter + crop-resize ----------------
__global__ void __launch_bounds__(256, 6) aug_kernel(const float* __restrict__ img,
                                                  const float* __restrict__ u_jitter,
                                                  const float* __restrict__ u_bright,
                                                  const float* __restrict__ u_contrast,
                                                  const float* __restrict__ u_sat,
                                                  const float* __restrict__ u_hue,
                                                  const float* __restrict__ u_crop,
                                                  const float* __restrict__ u_scale,
                                                  const float* __restrict__ u_top,
                                                  const float* __restrict__ u_left,
                                                  float* __restrict__ out)
{
    __shared__ float sm[3][SRC_ROWS][WW];   // 24192 B

    int b   = blockIdx.y;
    int ty0 = blockIdx.x * TILE_ROWS;

    bool jit = (u_jitter[b] < 0.8f);
    bool crp = (u_crop[b]   < 0.5f);

    float bf = 1.0f + (2.0f*u_bright[b]   - 1.0f)*0.2f;
    float cf = 1.0f + (2.0f*u_contrast[b] - 1.0f)*0.2f;
    float sf = 1.0f + (2.0f*u_sat[b]      - 1.0f)*0.2f;
    float hb = 1.0f + (2.0f*u_hue[b] - 1.0f)*0.05f;     // 1 + hue
    float omsf = 1.0f - sf;
    float cm = 0.0f;
    if (jit) {
        float acc = 0.0f;
        #pragma unroll
        for (int k = 0; k < PARTS; k++) acc += g_partial[b*PARTS+k];
        cm = (1.0f - cf) * (acc * (1.0f/(float)HW));
    }

    const float* src = img + (size_t)b*3*HW;
    float*       dst = out + (size_t)b*3*HW;

    if (!crp) {
        // output = jittered (or raw) input rows, identity geometry
        const float4* s4 = (const float4*)src;
        float4*       d4 = (float4*)dst;
        if (!jit) {
            #pragma unroll
            for (int c = 0; c < 3; c++) {
                int base = (c*HW + ty0*WW) >> 2;
                for (int i = threadIdx.x; i < (TILE_ROWS*WW)>>2; i += blockDim.x)
                    d4[base+i] = s4[base+i];
            }
        } else {
            int base = (ty0*WW) >> 2;
            for (int i = threadIdx.x; i < (TILE_ROWS*WW)>>2; i += blockDim.x) {
                int p = base + i;
                float4 r4 = s4[p];
                float4 g4 = s4[(HW>>2)+p];
                float4 b4 = s4[(2*(HW>>2))+p];
                #pragma unroll
                for (int j = 0; j < 4; j++) {
                    float r  = ((const float*)&r4)[j];
                    float g  = ((const float*)&g4)[j];
                    float bl = ((const float*)&b4)[j];
                    jitter_px(r,g,bl, bf,cf,cm,sf,omsf,hb);
                    ((float*)&r4)[j] = r; ((float*)&g4)[j] = g; ((float*)&b4)[j] = bl;
                }
                d4[p] = r4;
                d4[(HW>>2)+p] = g4;
                d4[(2*(HW>>2))+p] = b4;
            }
        }
        return;
    }

    // ---- crop geometry: must match JAX fp32 op-for-op (floor decisions) ----
    float scale = __fadd_rn(0.85f, __fmul_rn((1.0f - 0.85f), u_scale[b]));
    float chf   = floorf(__fmul_rn(224.0f, scale));
    float cwf   = chf;   // H == W
    float hm    = __fadd_rn(__fsub_rn(224.0f, chf), 1.0f);
    float topf  = fminf(fmaxf(floorf(__fmul_rn(u_top[b],  hm)), 0.0f), 224.0f - chf);
    float leftf = fminf(fmaxf(floorf(__fmul_rn(u_left[b], hm)), 0.0f), 224.0f - cwf);

    const float inv224 = 1.0f/224.0f;

    // source row window for this tile (ys monotone in y; same formula as loop below)
    float ys0 = fminf(fmaxf(topf + ((float)ty0 + 0.5f)*chf*inv224 - 0.5f, 0.0f), 223.0f);
    int ry0 = (int)floorf(ys0);

    // ---- phase 1: load + jitter SRC_ROWS x 224 slab into smem ----
    for (int idx = threadIdx.x; idx < SRC_ROWS*WW; idx += blockDim.x) {
        int row = idx / WW;
        int col = idx - row*WW;
        int srow = min(ry0 + row, HH-1);
        int p = srow*WW + col;
        float r = src[p], g = src[HW+p], bl = src[2*HW+p];
        if (jit) jitter_px(r,g,bl, bf,cf,cm,sf,omsf,hb);
        sm[0][row][col] = r;
        sm[1][row][col] = g;
        sm[2][row][col] = bl;
    }
    __syncthreads();

    // ---- phase 2: bilinear sample TILE_ROWS x 224 output, 4 px per thread ----
    for (int idx = threadIdx.x; idx < TILE_ROWS*W4; idx += blockDim.x) {
        int ry = idx / W4;
        int c4 = idx - ry*W4;
        int oy = ty0 + ry;
        float ys = fminf(fmaxf(topf + ((float)oy + 0.5f)*chf*inv224 - 0.5f, 0.0f), 223.0f);
        float y0f = floorf(ys);
        float wy  = ys - y0f;
        int y0 = (int)y0f - ry0;
        int y1 = min((int)y0f + 1, HH-1) - ry0;

        int   x0[4], x1[4];
        float wx[4];
        #pragma unroll
        for (int j = 0; j < 4; j++) {
            int ox = c4*4 + j;
            float xs = fminf(fmaxf(leftf + ((float)ox + 0.5f)*cwf*inv224 - 0.5f, 0.0f), 223.0f);
            float x0f = floorf(xs);
            wx[j] = xs - x0f;
            x0[j] = (int)x0f;
            x1[j] = min(x0[j] + 1, WW-1);
        }

        float4* d4 = (float4*)dst;
        int po4 = oy*W4 + c4;
        #pragma unroll
        for (int c = 0; c < 3; c++) {
            float4 o;
            #pragma unroll
            for (int j = 0; j < 4; j++) {
                float a  = sm[c][y0][x0[j]], bq = sm[c][y0][x1[j]];
                float cq = sm[c][y1][x0[j]], dq = sm[c][y1][x1[j]];
                float row0 = fmaf(wx[j], bq - a,  a);
                float row1 = fmaf(wx[j], dq - cq, cq);
                ((float*)&o)[j] = fmaf(wy, row1 - row0, row0);
            }
            d4[c*(HW>>2) + po4] = o;
        }
    }
}

extern "C" void kernel_launch(void* const* d_in, const int* in_sizes, int n_in,
                              void* d_out, int out_size)
{
    const float* img        = (const float*)d_in[0];
    const float* u_jitter   = (const float*)d_in[1];
    const float* u_bright   = (const float*)d_in[2];
    const float* u_contrast = (const float*)d_in[3];
    const float* u_sat      = (const float*)d_in[4];
    const float* u_hue      = (const float*)d_in[5];
    const float* u_crop     = (const float*)d_in[6];
    const float* u_scale    = (const float*)d_in[7];
    const float* u_top      = (const float*)d_in[8];
    const float* u_left     = (const float*)d_in[9];
    float* out = (float*)d_out;

    dim3 g1(PARTS, BB);
    mean_kernel<<<g1, 256>>>(img, u_jitter, u_bright);

    dim3 g2(NTILES, BB);
    aug_kernel<<<g2, 256>>>(img, u_jitter, u_bright, u_contrast, u_sat, u_hue,
                            u_crop, u_scale, u_top, u_left, out);
}

// round 11
// speedup vs baseline: 1.1510x; 1.0584x over previous
#include <cuda_runtime.h>

#define BB 256
#define HH 224
#define WW 224
#define HW (HH*WW)          // 50176
#define W4 (WW/4)           // 56
#define PARTS 7
#define ROWS_PER_PART (HH/PARTS)   // 32
#define TILE_ROWS 8
#define SRC_ROWS 9
#define NTILES (HH/TILE_ROWS)      // 28

__device__ float g_partial[BB*PARTS];

// ---------------- Kernel 1: per-image mean of grayscale(clip(bf*img)) ----------------
__global__ void __launch_bounds__(256) mean_kernel(const float* __restrict__ img,
                                                   const float* __restrict__ u_jitter,
                                                   const float* __restrict__ u_bright)
{
    int b = blockIdx.y;
    int part = blockIdx.x;
    __shared__ float red[8];
    if (u_jitter[b] >= 0.8f) {           // mean unused for jitter-off images
        if (threadIdx.x == 0) g_partial[b*PARTS+part] = 0.0f;
        return;
    }
    float bf = 1.0f + (2.0f*u_bright[b] - 1.0f)*0.2f;
    const float4* base = (const float4*)(img + (size_t)b*3*HW);
    int p0 = (part*ROWS_PER_PART*WW) >> 2;
    const int N4 = (ROWS_PER_PART*WW) >> 2;   // 1792
    float sum = 0.0f;
    for (int i = threadIdx.x; i < N4; i += blockDim.x) {
        int p = p0 + i;
        float4 r4 = base[p];
        float4 g4 = base[(HW>>2)+p];
        float4 b4 = base[(2*(HW>>2))+p];
        #pragma unroll
        for (int j = 0; j < 4; j++) {
            float r  = __saturatef(bf*((const float*)&r4)[j]);
            float g  = __saturatef(bf*((const float*)&g4)[j]);
            float bl = __saturatef(bf*((const float*)&b4)[j]);
            sum += 0.299f*r + 0.587f*g + 0.114f*bl;
        }
    }
    // warp + smem reduce
    #pragma unroll
    for (int s = 16; s > 0; s >>= 1) sum += __shfl_xor_sync(0xffffffffu, sum, s);
    if ((threadIdx.x & 31) == 0) red[threadIdx.x >> 5] = sum;
    __syncthreads();
    if (threadIdx.x < 8) {
        float v = red[threadIdx.x];
        #pragma unroll
        for (int s = 4; s > 0; s >>= 1) v += __shfl_xor_sync(0xffu, v, s);
        if (threadIdx.x == 0) g_partial[b*PARTS+part] = v;
    }
}

// ---------------- color jitter for one pixel (streamlined v2) ----------------
// cm = (1-cf)*mg, omsf = 1-sf, hb = 1 + hue   (hoisted per image)
__device__ __forceinline__ void jitter_px(float& r, float& g, float& bl,
                                          float bf, float cf, float cm,
                                          float sf, float omsf, float hb)
{
    // brightness blend with zeros (saturate folds into the MUL)
    r = __saturatef(bf*r); g = __saturatef(bf*g); bl = __saturatef(bf*bl);
    // contrast blend with mean gray
    r  = __saturatef(fmaf(cf, r,  cm));
    g  = __saturatef(fmaf(cf, g,  cm));
    bl = __saturatef(fmaf(cf, bl, cm));
    // saturation blend with per-pixel gray
    float gray = fmaf(0.299f, r, fmaf(0.587f, g, 0.114f*bl));
    float sg = omsf*gray;
    r  = __saturatef(fmaf(sf, r,  sg));
    g  = __saturatef(fmaf(sf, g,  sg));
    bl = __saturatef(fmaf(sf, bl, sg));
    // hue rotate: RGB -> (h, v, chroma) -> shift -> RGB (branch-free, v*s == chroma)
    float maxc = fmaxf(fmaxf(r,g),bl);
    float minc = fminf(fminf(r,g),bl);
    float v  = maxc;
    float cr = maxc - minc;
    float inv = __fdividef(1.0f, (cr == 0.0f) ? 1.0f : cr);
    // delta-form sector offset: (bc-gc)=(g-b)*inv, (2+rc-bc)=2+(b-r)*inv, (4+gc-rc)=4+(r-g)*inv
    float d    = (maxc == r) ? (g - bl) : (maxc == g) ? (bl - r) : (r - g);
    float base = (maxc == r) ? 0.0f     : (maxc == g) ? 2.0f     : 4.0f;
    float h = fmaf(fmaf(d, inv, base), 1.0f/6.0f, hb);   // h0/6 + 1 + hue
    h -= floorf(h);
    float h6 = h*6.0f;                      // in [0, 6)
    // out_n = v - chroma * clamp01(min(k, 4-k)),  k = (n + h6) mod 6
    float kr = 5.0f + h6; kr = (kr >= 6.0f) ? (kr - 6.0f) : kr;
    float kg = 3.0f + h6; kg = (kg >= 6.0f) ? (kg - 6.0f) : kg;
    float kb = 1.0f + h6; kb = (kb >= 6.0f) ? (kb - 6.0f) : kb;
    r  = __saturatef(fmaf(-cr, __saturatef(fminf(kr, 4.0f - kr)), v));
    g  = __saturatef(fmaf(-cr, __saturatef(fminf(kg, 4.0f - kg)), v));
    bl = __saturatef(fmaf(-cr, __saturatef(fminf(kb, 4.0f - kb)), v));
}

// ---------------- Kernel 2: fused jitter + crop-resize ----------------
__global__ void __launch_bounds__(256, 6) aug_kernel(const float* __restrict__ img,
                                                  const float* __restrict__ u_jitter,
                                                  const float* __restrict__ u_bright,
                                                  const float* __restrict__ u_contrast,
                                                  const float* __restrict__ u_sat,
                                                  const float* __restrict__ u_hue,
                                                  const float* __restrict__ u_crop,
                                                  const float* __restrict__ u_scale,
                                                  const float* __restrict__ u_top,
                                                  const float* __restrict__ u_left,
                                                  float* __restrict__ out)
{
    __shared__ float sm[3][SRC_ROWS][WW];   // 24192 B

    int b   = blockIdx.y;
    int ty0 = blockIdx.x * TILE_ROWS;

    bool jit = (u_jitter[b] < 0.8f);
    bool crp = (u_crop[b]   < 0.5f);

    float bf = 1.0f + (2.0f*u_bright[b]   - 1.0f)*0.2f;
    float cf = 1.0f + (2.0f*u_contrast[b] - 1.0f)*0.2f;
    float sf = 1.0f + (2.0f*u_sat[b]      - 1.0f)*0.2f;
    float hb = 1.0f + (2.0f*u_hue[b] - 1.0f)*0.05f;     // 1 + hue
    float omsf = 1.0f - sf;
    float cm = 0.0f;
    if (jit) {
        float acc = 0.0f;
        #pragma unroll
        for (int k = 0; k < PARTS; k++) acc += g_partial[b*PARTS+k];
        cm = (1.0f - cf) * (acc * (1.0f/(float)HW));
    }

    const float* src = img + (size_t)b*3*HW;
    float*       dst = out + (size_t)b*3*HW;

    if (!crp) {
        // output = jittered (or raw) input rows, identity geometry
        const float4* s4 = (const float4*)src;
        float4*       d4 = (float4*)dst;
        if (!jit) {
            #pragma unroll
            for (int c = 0; c < 3; c++) {
                int base = (c*HW + ty0*WW) >> 2;
                for (int i = threadIdx.x; i < (TILE_ROWS*WW)>>2; i += blockDim.x)
                    d4[base+i] = s4[base+i];
            }
        } else {
            int base = (ty0*WW) >> 2;
            for (int i = threadIdx.x; i < (TILE_ROWS*WW)>>2; i += blockDim.x) {
                int p = base + i;
                float4 r4 = s4[p];
                float4 g4 = s4[(HW>>2)+p];
                float4 b4 = s4[(2*(HW>>2))+p];
                #pragma unroll
                for (int j = 0; j < 4; j++) {
                    float r  = ((const float*)&r4)[j];
                    float g  = ((const float*)&g4)[j];
                    float bl = ((const float*)&b4)[j];
                    jitter_px(r,g,bl, bf,cf,cm,sf,omsf,hb);
                    ((float*)&r4)[j] = r; ((float*)&g4)[j] = g; ((float*)&b4)[j] = bl;
                }
                d4[p] = r4;
                d4[(HW>>2)+p] = g4;
                d4[(2*(HW>>2))+p] = b4;
            }
        }
        return;
    }

    // ---- crop geometry: must match JAX fp32 op-for-op (floor decisions) ----
    float scale = __fadd_rn(0.85f, __fmul_rn((1.0f - 0.85f), u_scale[b]));
    float chf   = floorf(__fmul_rn(224.0f, scale));
    float cwf   = chf;   // H == W
    float hm    = __fadd_rn(__fsub_rn(224.0f, chf), 1.0f);
    float topf  = fminf(fmaxf(floorf(__fmul_rn(u_top[b],  hm)), 0.0f), 224.0f - chf);
    float leftf = fminf(fmaxf(floorf(__fmul_rn(u_left[b], hm)), 0.0f), 224.0f - cwf);

    const float inv224 = 1.0f/224.0f;

    // source row window for this tile (ys monotone in y; same formula as loop below)
    float ys0 = fminf(fmaxf(topf + ((float)ty0 + 0.5f)*chf*inv224 - 0.5f, 0.0f), 223.0f);
    int ry0 = (int)floorf(ys0);

    // ---- phase 1: load + jitter SRC_ROWS x 224 slab into smem (float4 granularity) ----
    {
        const int NQ = (SRC_ROWS*WW) >> 2;   // 504
        const float4* s4 = (const float4*)src;
        for (int idx = threadIdx.x; idx < NQ; idx += blockDim.x) {
            int row = idx / W4;              // W4 = 56 float4s per row
            int c4  = idx - row*W4;
            int srow = min(ry0 + row, HH-1);
            int p = srow*W4 + c4;            // float4 index within channel
            float4 r4 = s4[p];
            float4 g4 = s4[(HW>>2)+p];
            float4 b4 = s4[(2*(HW>>2))+p];
            if (jit) {
                #pragma unroll
                for (int j = 0; j < 4; j++) {
                    float r  = ((const float*)&r4)[j];
                    float g  = ((const float*)&g4)[j];
                    float bl = ((const float*)&b4)[j];
                    jitter_px(r,g,bl, bf,cf,cm,sf,omsf,hb);
                    ((float*)&r4)[j] = r; ((float*)&g4)[j] = g; ((float*)&b4)[j] = bl;
                }
            }
            int col = c4*4;
            *(float4*)&sm[0][row][col] = r4;
            *(float4*)&sm[1][row][col] = g4;
            *(float4*)&sm[2][row][col] = b4;
        }
    }
    __syncthreads();

    // ---- phase 2: bilinear sample TILE_ROWS x 224 output, 4 px per thread ----
    for (int idx = threadIdx.x; idx < TILE_ROWS*W4; idx += blockDim.x) {
        int ry = idx / W4;
        int c4 = idx - ry*W4;
        int oy = ty0 + ry;
        float ys = fminf(fmaxf(topf + ((float)oy + 0.5f)*chf*inv224 - 0.5f, 0.0f), 223.0f);
        float y0f = floorf(ys);
        float wy  = ys - y0f;
        int y0 = (int)y0f - ry0;
        int y1 = min((int)y0f + 1, HH-1) - ry0;

        int   x0[4], x1[4];
        float wx[4];
        #pragma unroll
        for (int j = 0; j < 4; j++) {
            int ox = c4*4 + j;
            float xs = fminf(fmaxf(leftf + ((float)ox + 0.5f)*cwf*inv224 - 0.5f, 0.0f), 223.0f);
            float x0f = floorf(xs);
            wx[j] = xs - x0f;
            x0[j] = (int)x0f;
            x1[j] = min(x0[j] + 1, WW-1);
        }

        float4* d4 = (float4*)dst;
        int po4 = oy*W4 + c4;
        #pragma unroll
        for (int c = 0; c < 3; c++) {
            float4 o;
            #pragma unroll
            for (int j = 0; j < 4; j++) {
                float a  = sm[c][y0][x0[j]], bq = sm[c][y0][x1[j]];
                float cq = sm[c][y1][x0[j]], dq = sm[c][y1][x1[j]];
                float row0 = fmaf(wx[j], bq - a,  a);
                float row1 = fmaf(wx[j], dq - cq, cq);
                ((float*)&o)[j] = fmaf(wy, row1 - row0, row0);
            }
            d4[c*(HW>>2) + po4] = o;
        }
    }
}

extern "C" void kernel_launch(void* const* d_in, const int* in_sizes, int n_in,
                              void* d_out, int out_size)
{
    const float* img        = (const float*)d_in[0];
    const float* u_jitter   = (const float*)d_in[1];
    const float* u_bright   = (const float*)d_in[2];
    const float* u_contrast = (const float*)d_in[3];
    const float* u_sat      = (const float*)d_in[4];
    const float* u_hue      = (const float*)d_in[5];
    const float* u_crop     = (const float*)d_in[6];
    const float* u_scale    = (const float*)d_in[7];
    const float* u_top      = (const float*)d_in[8];
    const float* u_left     = (const float*)d_in[9];
    float* out = (float*)d_out;

    dim3 g1(PARTS, BB);
    mean_kernel<<<g1, 256>>>(img, u_jitter, u_bright);

    dim3 g2(NTILES, BB);
    aug_kernel<<<g2, 256>>>(img, u_jitter, u_bright, u_contrast, u_sat, u_hue,
                            u_crop, u_scale, u_top, u_left, out);
}